// round 1
// baseline (speedup 1.0000x reference)
#include <cuda_runtime.h>
#include <math.h>

#define BATCH 256
#define CH    64          // channels C
#define MDIM  4096        // samples M
#define TM    64          // m-tile
#define NT    256         // threads per CTA
#define NTILES (MDIM/TM)
#define LDT   68          // tile row stride (floats), 16B aligned, padded
#define LDC   65          // cov row stride (floats) -> conflict-free columns
#define LDW   68          // Wt row stride

// flipped accessor for UL-via-Cholesky
#define A_(i,j) covb[(63-(i))*LDC + (63-(j))]

__global__ __launch_bounds__(NT)
void cnc_kernel(const float* __restrict__ x, float* __restrict__ z)
{
    __shared__ __align__(16) float bufA[CH*LDT];   // xt (phase A) / cov (phase B) / x-tile (phase C)
    __shared__ __align__(16) float Wt[CH*LDW];     // Wt[d][r] = W[r][d]
    __shared__ float s_part[CH][4];
    __shared__ float s_mu[CH];
    __shared__ float s_invd[CH];
    __shared__ float s_w[8][2];
    __shared__ float s_bc[2];                      // broadcast scalars

    float* covb = bufA;                            // cov view, stride LDC

    const int b   = blockIdx.x;
    const int tid = threadIdx.x;
    const float* xb = x + (size_t)b * CH * MDIM;
    float*       zb = z + (size_t)b * CH * MDIM;

    // ---- triangular 4x4-block mapping for tid < 136 (16x16 block grid, upper incl diag)
    int bi = 0, bj = 0;
    {
        int t = tid, r = 0;
        while (r < 16 && t >= 16 - r) { t -= 16 - r; r++; }
        bi = r; bj = r + t;                        // valid only when tid < 136
    }

    const int lc = tid >> 2;                       // load row (channel)
    const int lq = tid & 3;                       // load quarter along m

    // =================== Phase A: Gram + row sums ===================
    float acc[4][4];
#pragma unroll
    for (int i = 0; i < 4; i++)
#pragma unroll
        for (int j = 0; j < 4; j++) acc[i][j] = 0.f;
    float ssum = 0.f;

    for (int t = 0; t < NTILES; ++t) {
        const int m0 = t * TM;
        __syncthreads();
        // load 16 floats of row lc, store transposed xt[j][lc]
        const float4* src = (const float4*)(xb + (size_t)lc * MDIM + m0 + lq * 16);
#pragma unroll
        for (int v = 0; v < 4; ++v) {
            float4 d = src[v];
            ssum += (d.x + d.y) + (d.z + d.w);
            int j = lq * 16 + v * 4;
            bufA[(j + 0) * LDT + lc] = d.x;
            bufA[(j + 1) * LDT + lc] = d.y;
            bufA[(j + 2) * LDT + lc] = d.z;
            bufA[(j + 3) * LDT + lc] = d.w;
        }
        __syncthreads();
        if (tid < 136) {
#pragma unroll 8
            for (int j = 0; j < TM; ++j) {
                float4 a  = *(const float4*)&bufA[j * LDT + 4 * bi];
                float4 c4 = *(const float4*)&bufA[j * LDT + 4 * bj];
                acc[0][0] += a.x*c4.x; acc[0][1] += a.x*c4.y; acc[0][2] += a.x*c4.z; acc[0][3] += a.x*c4.w;
                acc[1][0] += a.y*c4.x; acc[1][1] += a.y*c4.y; acc[1][2] += a.y*c4.z; acc[1][3] += a.y*c4.w;
                acc[2][0] += a.z*c4.x; acc[2][1] += a.z*c4.y; acc[2][2] += a.z*c4.z; acc[2][3] += a.z*c4.w;
                acc[3][0] += a.w*c4.x; acc[3][1] += a.w*c4.y; acc[3][2] += a.w*c4.z; acc[3][3] += a.w*c4.w;
            }
        }
    }

    // deterministic row-sum reduction -> mu
    s_part[lc][lq] = ssum;
    __syncthreads();
    if (tid < CH) {
        float s0 = ((s_part[tid][0] + s_part[tid][1]) + s_part[tid][2]) + s_part[tid][3];
        s_mu[tid] = s0 * (1.f / MDIM);
    }
    __syncthreads();   // also: all Gram reads of bufA done -> safe to overwrite with cov

    // cov = G/M - mu mu^T  (write both triangles)
    if (tid < 136) {
        const float invM = 1.f / MDIM;
#pragma unroll
        for (int i = 0; i < 4; i++) {
            float mui = s_mu[4 * bi + i];
#pragma unroll
            for (int j = 0; j < 4; j++) {
                float v = acc[i][j] * invM - mui * s_mu[4 * bj + j];
                covb[(4 * bi + i) * LDC + (4 * bj + j)] = v;
                covb[(4 * bj + j) * LDC + (4 * bi + i)] = v;
            }
        }
    }
    __syncthreads();

    // =================== Phase B: shrinkage + flipped Cholesky + tri-inverse ===================
    // deterministic reductions for trace and Frobenius^2
    float tr_p = 0.f, fr_p = 0.f;
    for (int idx = tid; idx < CH * CH; idx += NT) {
        int i = idx >> 6, j = idx & 63;
        float v = covb[i * LDC + j];
        fr_p += v * v;
        if (i == j) tr_p += v;
    }
#pragma unroll
    for (int o = 16; o; o >>= 1) {
        tr_p += __shfl_down_sync(0xffffffffu, tr_p, o);
        fr_p += __shfl_down_sync(0xffffffffu, fr_p, o);
    }
    if ((tid & 31) == 0) { s_w[tid >> 5][0] = tr_p; s_w[tid >> 5][1] = fr_p; }
    __syncthreads();
    if (tid == 0) {
        float tr = 0.f, st = 0.f;
#pragma unroll
        for (int w = 0; w < 8; w++) { tr += s_w[w][0]; st += s_w[w][1]; }
        const float n = (float)MDIM, p = (float)CH;
        float num = (n - 2.f) / n * st + tr * tr;
        float den = (n + 2.f) * (st - tr * tr / p);
        float rho = fminf(num / den, 1.f);
        s_bc[0] = rho;
        s_bc[1] = rho * tr / p;     // diagonal addition
    }
    __syncthreads();
    {
        const float rho = s_bc[0], dadd = s_bc[1];
        for (int idx = tid; idx < CH * CH; idx += NT) {
            int i = idx >> 6, j = idx & 63;
            float v = covb[i * LDC + j] * (1.f - rho);
            if (i == j) v += dadd;
            covb[i * LDC + j] = v;
        }
    }

    // in-place Cholesky on flipped matrix: leaves U (upper, cov = U U^T) in natural layout
    for (int k = 0; k < CH; ++k) {
        __syncthreads();
        if (tid == 0) {
            float d  = A_(k, k);
            float sd = sqrtf(d);
            A_(k, k) = sd;
            s_bc[0]  = 1.f / sd;
        }
        __syncthreads();
        if (tid > k && tid < CH) A_(tid, k) *= s_bc[0];
        __syncthreads();
        // trailing update: i in (k,63], j in (k,i]
        {
            int ii = tid & 63, g = tid >> 6;
            int i = k + 1 + ii;
            if (i < CH) {
                float aik = A_(i, k);
                for (int j = k + 1 + g; j <= i; j += 4)
                    A_(i, j) -= aik * A_(j, k);
            }
        }
    }
    __syncthreads();

    if (tid < CH) s_invd[tid] = 1.f / covb[tid * LDC + tid];
    // zero Wt
    for (int idx = tid; idx < CH * LDW; idx += NT) Wt[idx] = 0.f;
    __syncthreads();

    // W = U^{-1} (upper). Column j per thread; store transposed Wt[j][i] = W[i][j].
    if (tid < CH) {
        const int j = tid;
        Wt[j * LDW + j] = s_invd[j];
        for (int i = j - 1; i >= 0; --i) {
            float a = 0.f;
            for (int k = i + 1; k <= j; ++k)
                a += covb[i * LDC + k] * Wt[j * LDW + k];
            Wt[j * LDW + i] = -a * s_invd[i];
        }
    }
    __syncthreads();

    // =================== Phase C: Z = W (x - mu) ===================
    const int ty = tid >> 4, tx = tid & 15;
    const int r0 = 4 * ty, c0 = 4 * tx;
    const float mu_c = s_mu[lc];

    for (int t = 0; t < NTILES; ++t) {
        const int m0 = t * TM;
        __syncthreads();  // previous tile consumers done (and, for t=0, Wt ready / cov dead)
        const float4* src = (const float4*)(xb + (size_t)lc * MDIM + m0 + lq * 16);
        float4* dst = (float4*)&bufA[lc * LDT + lq * 16];
#pragma unroll
        for (int v = 0; v < 4; ++v) {
            float4 d = src[v];
            d.x -= mu_c; d.y -= mu_c; d.z -= mu_c; d.w -= mu_c;
            dst[v] = d;
        }
        __syncthreads();

        float4 z0 = {0,0,0,0}, z1 = z0, z2 = z0, z3 = z0;
        for (int d = r0; d < CH; ++d) {
            float4 w  = *(const float4*)&Wt[d * LDW + r0];
            float4 xv = *(const float4*)&bufA[d * LDT + c0];
            z0.x += w.x*xv.x; z0.y += w.x*xv.y; z0.z += w.x*xv.z; z0.w += w.x*xv.w;
            z1.x += w.y*xv.x; z1.y += w.y*xv.y; z1.z += w.y*xv.z; z1.w += w.y*xv.w;
            z2.x += w.z*xv.x; z2.y += w.z*xv.y; z2.z += w.z*xv.z; z2.w += w.z*xv.w;
            z3.x += w.w*xv.x; z3.y += w.w*xv.y; z3.z += w.w*xv.z; z3.w += w.w*xv.w;
        }
        float* zr = zb + (size_t)r0 * MDIM + m0 + c0;
        *(float4*)(zr)            = z0;
        *(float4*)(zr + MDIM)     = z1;
        *(float4*)(zr + 2*MDIM)   = z2;
        *(float4*)(zr + 3*MDIM)   = z3;
    }
}

extern "C" void kernel_launch(void* const* d_in, const int* in_sizes, int n_in,
                              void* d_out, int out_size)
{
    const float* x = (const float*)d_in[0];
    float* z = (float*)d_out;
    cnc_kernel<<<BATCH, NT>>>(x, z);
}

// round 2
// speedup vs baseline: 1.4704x; 1.4704x over previous
#include <cuda_runtime.h>
#include <math.h>

#define BATCH 256
#define CH    64
#define MDIM  4096
#define NT    256

#define S1    8
#define M1    (MDIM/S1)        // 512 samples per gram CTA
#define LDT   68               // transposed tile stride

#define LDC   65               // cov stride
#define LDW   65               // Wt stride (kernel2 smem)

#define S2    8
#define TM3   128              // apply m-tile
#define T3    (MDIM/(S2*TM3))  // 4 tiles per apply CTA
#define LDX   132              // x tile stride
#define SMEM3 ((CH*LDX + CH*CH + CH)*4)

__device__ float g_gram[(size_t)BATCH*S1*CH*CH];
__device__ float g_sums[BATCH*S1*CH];
__device__ float g_W[(size_t)BATCH*CH*CH];
__device__ float g_mu[BATCH*CH];

// =============== Kernel 1: partial Gram + partial sums ===============
__global__ __launch_bounds__(NT)
void gram_kernel(const float* __restrict__ x)
{
    __shared__ __align__(16) float xt[CH*LDT];   // transposed tile xt[m][ch]
    __shared__ float s_part[CH][4];

    const int b = blockIdx.x, s = blockIdx.y, tid = threadIdx.x;
    const float* xb = x + (size_t)b * CH * MDIM + s * M1;

    // triangular 4x4-block mapping (tid < 136)
    int bi = 0, bj = 0;
    { int t = tid, r = 0; while (r < 16 && t >= 16 - r) { t -= 16 - r; r++; } bi = r; bj = r + t; }

    const int lc = tid >> 2, lq = tid & 3;

    float acc[4][4] = {};
    float ssum = 0.f;

    for (int t = 0; t < M1 / 64; ++t) {
        const int m0 = t * 64;
        __syncthreads();
        // lane-interleaved float4 loads (full 32B sectors per warp transaction)
        const float4* src = (const float4*)(xb + (size_t)lc * MDIM + m0);
#pragma unroll
        for (int v = 0; v < 4; ++v) {
            float4 d = src[lq + v * 4];
            ssum += (d.x + d.y) + (d.z + d.w);
            int j = lq * 4 + v * 16;
            xt[(j + 0) * LDT + lc] = d.x;
            xt[(j + 1) * LDT + lc] = d.y;
            xt[(j + 2) * LDT + lc] = d.z;
            xt[(j + 3) * LDT + lc] = d.w;
        }
        __syncthreads();
        if (tid < 136) {
#pragma unroll 8
            for (int j = 0; j < 64; ++j) {
                float4 a = *(const float4*)&xt[j * LDT + 4 * bi];
                float4 c = *(const float4*)&xt[j * LDT + 4 * bj];
                acc[0][0] += a.x*c.x; acc[0][1] += a.x*c.y; acc[0][2] += a.x*c.z; acc[0][3] += a.x*c.w;
                acc[1][0] += a.y*c.x; acc[1][1] += a.y*c.y; acc[1][2] += a.y*c.z; acc[1][3] += a.y*c.w;
                acc[2][0] += a.z*c.x; acc[2][1] += a.z*c.y; acc[2][2] += a.z*c.z; acc[2][3] += a.z*c.w;
                acc[3][0] += a.w*c.x; acc[3][1] += a.w*c.y; acc[3][2] += a.w*c.z; acc[3][3] += a.w*c.w;
            }
        }
    }

    s_part[lc][lq] = ssum;
    __syncthreads();
    if (tid < CH) {
        float t0 = ((s_part[tid][0] + s_part[tid][1]) + s_part[tid][2]) + s_part[tid][3];
        g_sums[(b * S1 + s) * CH + tid] = t0;
    }
    if (tid < 136) {
        float* gg = g_gram + (size_t)(b * S1 + s) * CH * CH;
#pragma unroll
        for (int i = 0; i < 4; i++)
#pragma unroll
            for (int j = 0; j < 4; j++)
                gg[(4 * bi + i) * CH + 4 * bj + j] = acc[i][j];
    }
}

// =============== Kernel 2: reduce + shrinkage + Cholesky + inverse ===============
#define A_(i,j) covb[(63-(i))*LDC + (63-(j))]

__global__ __launch_bounds__(NT)
void chol_kernel()
{
    __shared__ float covb[CH*LDC];
    __shared__ float Wt[CH*LDW];     // Wt[d][r] = W[r][d]
    __shared__ float s_mu[CH];
    __shared__ float s_invd[CH];
    __shared__ float s_w[8][2];
    __shared__ float s_bc[2];

    const int b = blockIdx.x, tid = threadIdx.x;

    if (tid < CH) {
        float m = 0.f;
#pragma unroll
        for (int s = 0; s < S1; s++) m += g_sums[(b * S1 + s) * CH + tid];
        s_mu[tid] = m * (1.f / MDIM);
    }
    __syncthreads();

    for (int idx = tid; idx < CH * CH; idx += NT) {
        int i = idx >> 6, j = idx & 63;
        if (i <= j) {
            float g = 0.f;
#pragma unroll
            for (int s = 0; s < S1; s++) g += g_gram[(size_t)(b * S1 + s) * CH * CH + idx];
            float v = g * (1.f / MDIM) - s_mu[i] * s_mu[j];
            covb[i * LDC + j] = v;
            covb[j * LDC + i] = v;
        }
    }
    __syncthreads();

    // trace / Frobenius^2 (deterministic)
    float tr_p = 0.f, fr_p = 0.f;
    for (int idx = tid; idx < CH * CH; idx += NT) {
        int i = idx >> 6, j = idx & 63;
        float v = covb[i * LDC + j];
        fr_p += v * v;
        if (i == j) tr_p += v;
    }
#pragma unroll
    for (int o = 16; o; o >>= 1) {
        tr_p += __shfl_down_sync(0xffffffffu, tr_p, o);
        fr_p += __shfl_down_sync(0xffffffffu, fr_p, o);
    }
    if ((tid & 31) == 0) { s_w[tid >> 5][0] = tr_p; s_w[tid >> 5][1] = fr_p; }
    __syncthreads();
    if (tid == 0) {
        float tr = 0.f, st = 0.f;
#pragma unroll
        for (int w = 0; w < 8; w++) { tr += s_w[w][0]; st += s_w[w][1]; }
        const float n = (float)MDIM, p = (float)CH;
        float num = (n - 2.f) / n * st + tr * tr;
        float den = (n + 2.f) * (st - tr * tr / p);
        float rho = fminf(num / den, 1.f);
        s_bc[0] = rho;
        s_bc[1] = rho * tr / p;
    }
    __syncthreads();
    {
        const float rho = s_bc[0], dadd = s_bc[1];
        for (int idx = tid; idx < CH * CH; idx += NT) {
            int i = idx >> 6, j = idx & 63;
            float v = covb[i * LDC + j] * (1.f - rho);
            if (i == j) v += dadd;
            covb[i * LDC + j] = v;
        }
    }

    // flipped Cholesky -> U (upper, cov = U U^T) in natural indexing
    for (int k = 0; k < CH; ++k) {
        __syncthreads();
        if (tid == 0) {
            float d = A_(k, k);
            float sd = sqrtf(d);
            A_(k, k) = sd;
            s_bc[0] = 1.f / sd;
        }
        __syncthreads();
        if (tid > k && tid < CH) A_(tid, k) *= s_bc[0];
        __syncthreads();
        {
            int ii = tid & 63, g = tid >> 6;
            int i = k + 1 + ii;
            if (i < CH) {
                float aik = A_(i, k);
                for (int j = k + 1 + g; j <= i; j += 4)
                    A_(i, j) -= aik * A_(j, k);
            }
        }
    }
    __syncthreads();

    if (tid < CH) s_invd[tid] = 1.f / covb[tid * LDC + tid];
    for (int idx = tid; idx < CH * LDW; idx += NT) Wt[idx] = 0.f;
    __syncthreads();

    // W = U^{-1}: thread j computes column j, stores Wt[j][i] = W[i][j]
    if (tid < CH) {
        const int j = tid;
        Wt[j * LDW + j] = s_invd[j];
        for (int i = j - 1; i >= 0; --i) {
            float a = 0.f;
            for (int k = i + 1; k <= j; ++k)
                a += covb[i * LDC + k] * Wt[j * LDW + k];
            Wt[j * LDW + i] = -a * s_invd[i];
        }
    }
    __syncthreads();

    for (int idx = tid; idx < CH * CH; idx += NT) {
        int d = idx >> 6, r = idx & 63;
        g_W[(size_t)b * CH * CH + idx] = Wt[d * LDW + r];
    }
    if (tid < CH) g_mu[b * CH + tid] = s_mu[tid];
}

// =============== Kernel 3: Z = W (x - mu) ===============
extern __shared__ float smem3[];

__global__ __launch_bounds__(NT)
void apply_kernel(const float* __restrict__ x, float* __restrict__ z)
{
    float* xs = smem3;                 // [CH][LDX]
    float* Ws = smem3 + CH * LDX;      // [CH][CH], Ws[d][r] = W[r][d]
    float* mu = Ws + CH * CH;

    const int b = blockIdx.x, s = blockIdx.y, tid = threadIdx.x;
    const float* xb = x + (size_t)b * CH * MDIM;
    float*       zb = z + (size_t)b * CH * MDIM;

    {
        const float4* src = (const float4*)(g_W + (size_t)b * CH * CH);
        float4* dst = (float4*)Ws;
        for (int i = tid; i < CH * CH / 4; i += NT) dst[i] = src[i];
    }
    if (tid < CH) mu[tid] = g_mu[b * CH + tid];

    const int lc = tid >> 2, lq = tid & 3;
    const int ty = tid >> 5, tx = tid & 31;
    const int r0 = 8 * ty, c0 = 4 * tx;
    __syncthreads();
    const float mu_c = mu[lc];

    for (int t = 0; t < T3; ++t) {
        const int m0 = s * (T3 * TM3) + t * TM3;
        if (t) __syncthreads();
        // load 64x128 tile, subtract mu; lane-interleaved float4
        const float4* src = (const float4*)(xb + (size_t)lc * MDIM + m0);
        {
#pragma unroll
            for (int v = 0; v < 8; ++v) {
                float4 d = src[lq + v * 4];
                d.x -= mu_c; d.y -= mu_c; d.z -= mu_c; d.w -= mu_c;
                *(float4*)&xs[lc * LDX + lq * 4 + v * 16] = d;
            }
        }
        __syncthreads();

        float4 zz[8] = {};
#pragma unroll 4
        for (int d = r0; d < CH; ++d) {
            float4 w0 = *(const float4*)&Ws[d * CH + r0];       // warp-uniform broadcast
            float4 w1 = *(const float4*)&Ws[d * CH + r0 + 4];
            float4 xv = *(const float4*)&xs[d * LDX + c0];
            zz[0].x += w0.x*xv.x; zz[0].y += w0.x*xv.y; zz[0].z += w0.x*xv.z; zz[0].w += w0.x*xv.w;
            zz[1].x += w0.y*xv.x; zz[1].y += w0.y*xv.y; zz[1].z += w0.y*xv.z; zz[1].w += w0.y*xv.w;
            zz[2].x += w0.z*xv.x; zz[2].y += w0.z*xv.y; zz[2].z += w0.z*xv.z; zz[2].w += w0.z*xv.w;
            zz[3].x += w0.w*xv.x; zz[3].y += w0.w*xv.y; zz[3].z += w0.w*xv.z; zz[3].w += w0.w*xv.w;
            zz[4].x += w1.x*xv.x; zz[4].y += w1.x*xv.y; zz[4].z += w1.x*xv.z; zz[4].w += w1.x*xv.w;
            zz[5].x += w1.y*xv.x; zz[5].y += w1.y*xv.y; zz[5].z += w1.y*xv.z; zz[5].w += w1.y*xv.w;
            zz[6].x += w1.z*xv.x; zz[6].y += w1.z*xv.y; zz[6].z += w1.z*xv.z; zz[6].w += w1.z*xv.w;
            zz[7].x += w1.w*xv.x; zz[7].y += w1.w*xv.y; zz[7].z += w1.w*xv.z; zz[7].w += w1.w*xv.w;
        }
#pragma unroll
        for (int r = 0; r < 8; ++r)
            *(float4*)(zb + (size_t)(r0 + r) * MDIM + m0 + c0) = zz[r];
    }
}

extern "C" void kernel_launch(void* const* d_in, const int* in_sizes, int n_in,
                              void* d_out, int out_size)
{
    const float* x = (const float*)d_in[0];
    float* z = (float*)d_out;

    cudaFuncSetAttribute(apply_kernel, cudaFuncAttributeMaxDynamicSharedMemorySize, SMEM3);

    gram_kernel<<<dim3(BATCH, S1), NT>>>(x);
    chol_kernel<<<BATCH, NT>>>();
    apply_kernel<<<dim3(BATCH, S2), NT, SMEM3>>>(x, z);
}